// round 5
// baseline (speedup 1.0000x reference)
#include <cuda_runtime.h>
#include <cuda_fp16.h>

#define DIM 32
#define NODES_MAX 100000
#define EDGES_MAX 3200000
#define SCAN_BLK 1024
#define NB_MAX 128   // ceil(100000/1024)=98

// ---------------- scratch (device globals; no allocation allowed) ------------
// Invariant: g_deg is all-zero and g_pool all-zero at entry to kernel_launch
// (zero-initialized at load; k_scan1/k_head restore them every call).
__device__ __half g_p0[NODES_MAX * DIM];
__device__ __half g_p1[NODES_MAX * DIM];
__device__ int    g_deg[NODES_MAX];
__device__ int    g_row[NODES_MAX + 1];
__device__ int    g_wcur[NODES_MAX];
__device__ int    g_ssrc[EDGES_MAX];
__device__ int    g_bsum[NB_MAX];
__device__ float  g_pool[DIM];

// ---------------- CSR build --------------------------------------------------
__global__ void k_hist(const int* __restrict__ dst, int n_edges) {
    int stride = gridDim.x * blockDim.x;
    for (int i = blockIdx.x * blockDim.x + threadIdx.x; i < n_edges; i += stride)
        atomicAdd(&g_deg[__ldg(&dst[i])], 1);
}

// Block-local exclusive scan of degrees; also RESETS g_deg to zero for the
// next kernel_launch call (removes the need for a k_zero launch).
__global__ void k_scan1(int n_nodes) {
    __shared__ int s[SCAN_BLK];
    int tid = threadIdx.x;
    int i = blockIdx.x * SCAN_BLK + tid;
    int v = 0;
    if (i < n_nodes) { v = g_deg[i]; g_deg[i] = 0; }
    s[tid] = v;
    __syncthreads();
    for (int off = 1; off < SCAN_BLK; off <<= 1) {
        int t = (tid >= off) ? s[tid - off] : 0;
        __syncthreads();
        s[tid] += t;
        __syncthreads();
    }
    if (i < n_nodes) g_row[i] = s[tid] - v;  // local exclusive
    if (tid == SCAN_BLK - 1) g_bsum[blockIdx.x] = s[tid];
}

// Applies cross-block offsets (scanning the 98 block sums in smem locally)
// and initializes g_wcur. Replaces the old k_scan2 + k_scan3 pair.
__global__ void k_scan3(int n_nodes, int n_edges, int nb) {
    __shared__ int sb[NB_MAX];
    __shared__ int sex[NB_MAX];
    int tid = threadIdx.x;
    int v = 0;
    if (tid < NB_MAX) {
        v = (tid < nb) ? g_bsum[tid] : 0;
        sb[tid] = v;
    }
    __syncthreads();
    for (int off = 1; off < NB_MAX; off <<= 1) {
        int t = 0;
        if (tid < NB_MAX && tid >= off) t = sb[tid - off];
        __syncthreads();
        if (tid < NB_MAX) sb[tid] += t;
        __syncthreads();
    }
    if (tid < NB_MAX) sex[tid] = sb[tid] - v;  // exclusive
    __syncthreads();

    int stride = gridDim.x * blockDim.x;
    int gid = blockIdx.x * blockDim.x + tid;
    for (int i = gid; i < n_nodes; i += stride) {
        int r = g_row[i] + sex[i / SCAN_BLK];
        g_row[i] = r;
        g_wcur[i] = r;
    }
    if (gid == 0) g_row[n_nodes] = n_edges;
}

__global__ void k_fill(const int* __restrict__ src, const int* __restrict__ dst,
                       int n_edges) {
    int stride = gridDim.x * blockDim.x;
    for (int i = blockIdx.x * blockDim.x + threadIdx.x; i < n_edges; i += stride) {
        int pos = atomicAdd(&g_wcur[__ldg(&dst[i])], 1);
        g_ssrc[pos] = __ldg(&src[i]);
    }
}

// ---------------- input projection: p0 = x @ w1a (half output) ---------------
__global__ void k_proj(const float* __restrict__ x, const float* __restrict__ w1a,
                       int n_nodes, int in_dim) {
    __shared__ float ws[96 * DIM];
    for (int i = threadIdx.x; i < in_dim * DIM; i += blockDim.x) ws[i] = w1a[i];
    __syncthreads();
    int lane = threadIdx.x & 31;
    int warp = (blockIdx.x * blockDim.x + threadIdx.x) >> 5;
    int nwarp = (gridDim.x * blockDim.x) >> 5;
    for (int n = warp; n < n_nodes; n += nwarp) {
        const float* xr = x + (size_t)n * in_dim;
        float xv0 = (lane < in_dim) ? __ldg(&xr[lane]) : 0.0f;
        float xv1 = (32 + lane < in_dim) ? __ldg(&xr[32 + lane]) : 0.0f;
        float xv2 = (64 + lane < in_dim) ? __ldg(&xr[64 + lane]) : 0.0f;
        float acc = 0.0f;
        int k = 0;
        for (; k < min(in_dim, 32); k++)
            acc = fmaf(__shfl_sync(0xffffffffu, xv0, k), ws[k * DIM + lane], acc);
        for (; k < min(in_dim, 64); k++)
            acc = fmaf(__shfl_sync(0xffffffffu, xv1, k - 32), ws[k * DIM + lane], acc);
        for (; k < in_dim; k++)
            acc = fmaf(__shfl_sync(0xffffffffu, xv2, k - 64), ws[k * DIM + lane], acc);
        g_p0[n * DIM + lane] = __float2half(acc);
    }
}

// ---------------- fused GIN layer: 4 edges per warp-load, mask arithmetic ----
template <bool LAST>
__global__ void __launch_bounds__(256)
k_layer(const __half* __restrict__ p_in, __half* __restrict__ p_out,
        const float* __restrict__ Wb, const float* __restrict__ Bbv,
        const float* __restrict__ Bav, const float* __restrict__ Wanext,
        int n_nodes) {
    __shared__ float s_wb[DIM * DIM];
    __shared__ float s_wa[DIM * DIM];
    for (int i = threadIdx.x; i < DIM * DIM; i += blockDim.x) {
        s_wb[i] = Wb[i];
        if (!LAST) s_wa[i] = Wanext[i];
    }
    __syncthreads();

    const uint2* __restrict__ pu = (const uint2*)p_in;  // row = 8 uint2
    int lane = threadIdx.x & 31;
    int quad = lane >> 3;    // which of 4 edges this lane serves in a load
    int fq   = lane & 7;     // feature-quad index: features 4fq .. 4fq+3
    float4 ba4 = __ldg(&((const float4*)Bav)[fq]);
    float bbv = Bbv[lane];

    int warp = (blockIdx.x * blockDim.x + threadIdx.x) >> 5;
    int nwarp = (gridDim.x * blockDim.x) >> 5;
    float pool = 0.0f;

    for (int n = warp; n < n_nodes; n += nwarp) {
        int beg = g_row[n];
        int end = g_row[n + 1];
        uint2 svu = pu[n * 8 + fq];  // self row in flight early

        float a0x = 0.f, a0y = 0.f, a0z = 0.f, a0w = 0.f;
        float a1x = 0.f, a1y = 0.f, a1z = 0.f, a1w = 0.f;
        float a2x = 0.f, a2y = 0.f, a2z = 0.f, a2w = 0.f;
        float a3x = 0.f, a3y = 0.f, a3z = 0.f, a3w = 0.f;

        int lim = end - 1;
        for (int base = beg; base < end; base += 32) {
#define GATHER(J, AX, AY, AZ, AW)                                              \
            {                                                                  \
                int pos = base + 4 * (J) + quad;                               \
                int s = __ldg(&g_ssrc[min(pos, lim)]);                         \
                float m = (pos < end) ? 1.0f : 0.0f;                           \
                uint2 v = pu[s * 8 + fq];                                      \
                float2 lo = __half22float2(*(__half2*)&v.x);                   \
                float2 hi = __half22float2(*(__half2*)&v.y);                   \
                AX = fmaf(m, lo.x, AX); AY = fmaf(m, lo.y, AY);                \
                AZ = fmaf(m, hi.x, AZ); AW = fmaf(m, hi.y, AW);                \
            }
            GATHER(0, a0x, a0y, a0z, a0w)
            GATHER(1, a1x, a1y, a1z, a1w)
            GATHER(2, a2x, a2y, a2z, a2w)
            GATHER(3, a3x, a3y, a3z, a3w)
            GATHER(4, a0x, a0y, a0z, a0w)
            GATHER(5, a1x, a1y, a1z, a1w)
            GATHER(6, a2x, a2y, a2z, a2w)
            GATHER(7, a3x, a3y, a3z, a3w)
#undef GATHER
        }

        float t0 = (a0x + a1x) + (a2x + a3x);
        float t1 = (a0y + a1y) + (a2y + a3y);
        float t2 = (a0z + a1z) + (a2z + a3z);
        float t3 = (a0w + a1w) + (a2w + a3w);
        t0 += __shfl_xor_sync(0xffffffffu, t0, 8);
        t1 += __shfl_xor_sync(0xffffffffu, t1, 8);
        t2 += __shfl_xor_sync(0xffffffffu, t2, 8);
        t3 += __shfl_xor_sync(0xffffffffu, t3, 8);
        t0 += __shfl_xor_sync(0xffffffffu, t0, 16);
        t1 += __shfl_xor_sync(0xffffffffu, t1, 16);
        t2 += __shfl_xor_sync(0xffffffffu, t2, 16);
        t3 += __shfl_xor_sync(0xffffffffu, t3, 16);

        float2 slo = __half22float2(*(__half2*)&svu.x);
        float2 shi = __half22float2(*(__half2*)&svu.y);
        t0 = fmaxf(t0 + slo.x + ba4.x, 0.0f);
        t1 = fmaxf(t1 + slo.y + ba4.y, 0.0f);
        t2 = fmaxf(t2 + shi.x + ba4.z, 0.0f);
        t3 = fmaxf(t3 + shi.y + ba4.w, 0.0f);

        float u = bbv;
#pragma unroll
        for (int f = 0; f < 8; f++) {
            float c0 = __shfl_sync(0xffffffffu, t0, f);
            float c1 = __shfl_sync(0xffffffffu, t1, f);
            float c2 = __shfl_sync(0xffffffffu, t2, f);
            float c3 = __shfl_sync(0xffffffffu, t3, f);
            u = fmaf(c0, s_wb[(4 * f + 0) * DIM + lane], u);
            u = fmaf(c1, s_wb[(4 * f + 1) * DIM + lane], u);
            u = fmaf(c2, s_wb[(4 * f + 2) * DIM + lane], u);
            u = fmaf(c3, s_wb[(4 * f + 3) * DIM + lane], u);
        }
        u = fmaxf(u, 0.0f);

        if (!LAST) {
            float o = 0.0f;
#pragma unroll
            for (int k = 0; k < DIM; k++)
                o = fmaf(__shfl_sync(0xffffffffu, u, k), s_wa[k * DIM + lane], o);
            p_out[n * DIM + lane] = __float2half(o);
        } else {
            pool += u;
        }
    }

    if (LAST) {
        __shared__ float sp[8][DIM];
        int w = threadIdx.x >> 5;
        sp[w][lane] = pool;
        __syncthreads();
        if (w == 0) {
            float s = 0.0f;
#pragma unroll
            for (int i = 0; i < 8; i++) s += sp[i][lane];
            atomicAdd(&g_pool[lane], s);
        }
    }
}

// ---------------- head: consumes g_pool, then RESETS it for next call --------
__global__ void k_head(const float* __restrict__ fcw, const float* __restrict__ fcb,
                       const float* __restrict__ outw, const float* __restrict__ outb,
                       float* __restrict__ out) {
    __shared__ float g2[DIM];
    int j = threadIdx.x;
    float pv = g_pool[j];
    g_pool[j] = 0.0f;   // restore invariant for next kernel_launch call
    __syncwarp();
    __shared__ float gp[DIM];
    gp[j] = pv;
    __syncwarp();
    float acc = fcb[j];
    for (int k = 0; k < DIM; k++) acc = fmaf(gp[k], fcw[k * DIM + j], acc);
    g2[j] = fmaxf(acc, 0.0f);
    __syncwarp();
    float o = outb[j];
    for (int k = 0; k < DIM; k++) o = fmaf(g2[k], outw[k * DIM + j], o);
    out[j] = o;
}

// ---------------- launch ------------------------------------------------------
extern "C" void kernel_launch(void* const* d_in, const int* in_sizes, int n_in,
                              void* d_out, int out_size) {
    const float* x    = (const float*)d_in[0];
    const int*   ei   = (const int*)d_in[1];
    const float* w1a  = (const float*)d_in[2];
    const float* b1a  = (const float*)d_in[3];
    const float* w1b  = (const float*)d_in[4];
    const float* b1b  = (const float*)d_in[5];
    const float* wa   = (const float*)d_in[6];
    const float* ba   = (const float*)d_in[7];
    const float* wb   = (const float*)d_in[8];
    const float* bb   = (const float*)d_in[9];
    const float* fcw  = (const float*)d_in[10];
    const float* fcb  = (const float*)d_in[11];
    const float* outw = (const float*)d_in[12];
    const float* outb = (const float*)d_in[13];

    int in_dim  = in_sizes[2] / DIM;           // w1a is (in_dim, 32)
    int n_nodes = in_sizes[0] / in_dim;        // x is (n, in_dim)
    int n_edges = in_sizes[1] / 2;             // edge_index is (2, E)
    const int* src = ei;
    const int* dst = ei + n_edges;

    __half *p0, *p1;
    cudaGetSymbolAddress((void**)&p0, g_p0);
    cudaGetSymbolAddress((void**)&p1, g_p1);

    // CSR build (g_deg arrives zeroed; scan1 re-zeroes it)
    k_hist<<<2048, 256>>>(dst, n_edges);
    int nb = (n_nodes + SCAN_BLK - 1) / SCAN_BLK;
    k_scan1<<<nb, SCAN_BLK>>>(n_nodes);
    k_scan3<<<256, 256>>>(n_nodes, n_edges, nb);
    k_fill<<<2048, 256>>>(src, dst, n_edges);

    // projection to first-layer pre-aggregation space
    k_proj<<<1024, 256>>>(x, w1a, n_nodes, in_dim);

    // 5 fused GIN layers (double-buffered p)
    k_layer<false><<<2048, 256>>>(p0, p1, w1b, b1b, b1a, wa + 0 * DIM * DIM, n_nodes);
    k_layer<false><<<2048, 256>>>(p1, p0, wb + 0 * DIM * DIM, bb + 0 * DIM, ba + 0 * DIM,
                                  wa + 1 * DIM * DIM, n_nodes);
    k_layer<false><<<2048, 256>>>(p0, p1, wb + 1 * DIM * DIM, bb + 1 * DIM, ba + 1 * DIM,
                                  wa + 2 * DIM * DIM, n_nodes);
    k_layer<false><<<2048, 256>>>(p1, p0, wb + 2 * DIM * DIM, bb + 2 * DIM, ba + 2 * DIM,
                                  wa + 3 * DIM * DIM, n_nodes);
    k_layer<true><<<2048, 256>>>(p0, nullptr, wb + 3 * DIM * DIM, bb + 3 * DIM,
                                 ba + 3 * DIM, nullptr, n_nodes);

    // graph head (also resets g_pool)
    k_head<<<1, 32>>>(fcw, fcb, outw, outb, (float*)d_out);
}